// round 4
// baseline (speedup 1.0000x reference)
#include <cuda_runtime.h>

#define NCOL 2048
#define NROW 8192
#define T 256
#define V 8

__device__ float g_partial[NROW];

__device__ __forceinline__ void cswap_asc(float& a, float& b) {
    float lo = fminf(a, b);
    float hi = fmaxf(a, b);
    a = lo; b = hi;
}

// Arithmetic compare-exchange on the fma pipe: min=(s-|d|)/2, max=(s+|d|)/2.
// 1-ulp rounding vs FMNMX; irrelevant at rel tol 1e-3.
__device__ __forceinline__ void cswap_fma(float& a, float& b) {
    float s  = a + b;
    float d  = a - b;
    float hs = 0.5f * s;
    float hd = 0.5f * d;
    a = hs - fabsf(hd);
    b = hs + fabsf(hd);
}

__device__ __forceinline__ void cswap_desc(float& a, float& b) {
    float lo = fminf(a, b);
    float hi = fmaxf(a, b);
    a = hi; b = lo;
}

template<bool ARITH>
__device__ __forceinline__ void merge8_asc(float v[V]) {
    if (ARITH) {
        cswap_fma(v[0], v[4]); cswap_fma(v[1], v[5]);
        cswap_fma(v[2], v[6]); cswap_fma(v[3], v[7]);
        cswap_fma(v[0], v[2]); cswap_fma(v[1], v[3]);
        cswap_fma(v[4], v[6]); cswap_fma(v[5], v[7]);
        cswap_fma(v[0], v[1]); cswap_fma(v[2], v[3]);
        cswap_fma(v[4], v[5]); cswap_fma(v[6], v[7]);
    } else {
        cswap_asc(v[0], v[4]); cswap_asc(v[1], v[5]);
        cswap_asc(v[2], v[6]); cswap_asc(v[3], v[7]);
        cswap_asc(v[0], v[2]); cswap_asc(v[1], v[3]);
        cswap_asc(v[4], v[6]); cswap_asc(v[5], v[7]);
        cswap_asc(v[0], v[1]); cswap_asc(v[2], v[3]);
        cswap_asc(v[4], v[5]); cswap_asc(v[6], v[7]);
    }
}

__device__ __forceinline__ void sort8_pre(float v[V]) {
    cswap_asc (v[0], v[1]); cswap_desc(v[2], v[3]);
    cswap_asc (v[4], v[5]); cswap_desc(v[6], v[7]);
    cswap_asc (v[0], v[2]); cswap_asc (v[1], v[3]);
    cswap_desc(v[4], v[6]); cswap_desc(v[5], v[7]);
    cswap_asc (v[0], v[1]); cswap_asc (v[2], v[3]);
    cswap_desc(v[4], v[5]); cswap_desc(v[6], v[7]);
}

template<int KM>
__device__ __forceinline__ void flip_into(float yp[V], float yt[V], const int tid) {
    const bool flip = (((tid & KM) != 0) != ((tid & (KM >> 1)) != 0));
    const float s = flip ? -1.0f : 1.0f;
    #pragma unroll
    for (int e = 0; e < V; e++) { yp[e] *= s; yt[e] *= s; }
}

// One bitonic phase in ascending sign-space. TARITH: route the t-array's
// in-register tail comparators to the fma pipe (alu relief).
template<int KM, bool TARITH>
__device__ __forceinline__ void phase(float yp[V], float yt[V], const int tid,
                                      float2 (&buf)[NCOL]) {
    #pragma unroll
    for (int d = KM / 2; d >= 1; d >>= 1) {
        const bool keep_lo = ((tid & d) == 0);
        if (d >= 32) {
            // Cross-warp exchange through shared: p/t interleaved as float2.
            float4* s4 = (float4*)&buf[tid * V];
            s4[0] = make_float4(yp[0], yt[0], yp[1], yt[1]);
            s4[1] = make_float4(yp[2], yt[2], yp[3], yt[3]);
            s4[2] = make_float4(yp[4], yt[4], yp[5], yt[5]);
            s4[3] = make_float4(yp[6], yt[6], yp[7], yt[7]);
            __syncthreads();

            const int ptn = tid ^ d;
            const float4* o4 = (const float4*)&buf[ptn * V];
            float4 a = o4[0], b = o4[1], c = o4[2], e4 = o4[3];
            float op[V] = {a.x, a.z, b.x, b.z, c.x, c.z, e4.x, e4.z};
            float ot[V] = {a.y, a.w, b.y, b.w, c.y, c.w, e4.y, e4.w};

            #pragma unroll
            for (int e = 0; e < V; e++) {
                yp[e] = keep_lo ? fminf(yp[e], op[e]) : fmaxf(yp[e], op[e]);
                yt[e] = keep_lo ? fminf(yt[e], ot[e]) : fmaxf(yt[e], ot[e]);
            }
            __syncthreads();  // protect buf before next pass's writes
        } else {
            #pragma unroll
            for (int e = 0; e < V; e++) {
                float o1 = __shfl_xor_sync(0xFFFFFFFFu, yp[e], d);
                float o2 = __shfl_xor_sync(0xFFFFFFFFu, yt[e], d);
                yp[e] = keep_lo ? fminf(yp[e], o1) : fmaxf(yp[e], o1);
                yt[e] = keep_lo ? fminf(yt[e], o2) : fmaxf(yt[e], o2);
            }
        }
    }
    merge8_asc<false>(yp);
    merge8_asc<TARITH>(yt);
}

__global__ void nop_kernel() {}

__global__ __launch_bounds__(T)
void sort_mse_kernel(const float* __restrict__ pred,
                     const float* __restrict__ tgt) {
    __shared__ float2 buf[NCOL];
    __shared__ float swarp[T / 32];

    const int row = blockIdx.x;
    const int tid = threadIdx.x;

    float yp[V], yt[V];

    {
        const float4* p4 = (const float4*)(pred + (size_t)row * NCOL) + tid * 2;
        const float4* t4 = (const float4*)(tgt  + (size_t)row * NCOL) + tid * 2;
        float4 a = p4[0], b = p4[1];
        yp[0] = a.x; yp[1] = a.y; yp[2] = a.z; yp[3] = a.w;
        yp[4] = b.x; yp[5] = b.y; yp[6] = b.z; yp[7] = b.w;
        float4 c = t4[0], d = t4[1];
        yt[0] = c.x; yt[1] = c.y; yt[2] = c.z; yt[3] = c.w;
        yt[4] = d.x; yt[5] = d.y; yt[6] = d.z; yt[7] = d.w;
    }

    sort8_pre(yp);
    sort8_pre(yt);

    {
        const float s = (tid & 1) ? -1.0f : 1.0f;
        #pragma unroll
        for (int e = 0; e < V; e++) { yp[e] *= s; yt[e] *= s; }
    }
    merge8_asc<false>(yp);
    merge8_asc<false>(yt);

    flip_into<2>(yp, yt, tid);   phase<2,   false>(yp, yt, tid, buf);
    flip_into<4>(yp, yt, tid);   phase<4,   false>(yp, yt, tid, buf);
    flip_into<8>(yp, yt, tid);   phase<8,   false>(yp, yt, tid, buf);
    flip_into<16>(yp, yt, tid);  phase<16,  true >(yp, yt, tid, buf);
    flip_into<32>(yp, yt, tid);  phase<32,  true >(yp, yt, tid, buf);
    flip_into<64>(yp, yt, tid);  phase<64,  true >(yp, yt, tid, buf);
    flip_into<128>(yp, yt, tid); phase<128, true >(yp, yt, tid, buf);
    flip_into<256>(yp, yt, tid); phase<256, true >(yp, yt, tid, buf);

    float s = 0.0f;
    #pragma unroll
    for (int e = 0; e < V; e++) {
        float d = yp[e] - yt[e];
        s = fmaf(d, d, s);
    }

    #pragma unroll
    for (int off = 16; off > 0; off >>= 1)
        s += __shfl_xor_sync(0xFFFFFFFFu, s, off);

    const int lane = tid & 31;
    const int wid  = tid >> 5;
    if (lane == 0) swarp[wid] = s;
    __syncthreads();

    if (wid == 0) {
        float v = (lane < T / 32) ? swarp[lane] : 0.0f;
        #pragma unroll
        for (int off = 4; off > 0; off >>= 1)
            v += __shfl_xor_sync(0xFFFFFFFFu, v, off);
        if (lane == 0) g_partial[row] = v;
    }
}

__global__ void final_reduce_kernel(float* __restrict__ out) {
    __shared__ float swarp[32];
    const int tid = threadIdx.x;

    float s = 0.0f;
    #pragma unroll
    for (int i = tid; i < NROW; i += 1024)
        s += g_partial[i];

    #pragma unroll
    for (int off = 16; off > 0; off >>= 1)
        s += __shfl_xor_sync(0xFFFFFFFFu, s, off);

    const int lane = tid & 31;
    const int wid  = tid >> 5;
    if (lane == 0) swarp[wid] = s;
    __syncthreads();

    if (wid == 0) {
        float v = swarp[lane];
        #pragma unroll
        for (int off = 16; off > 0; off >>= 1)
            v += __shfl_xor_sync(0xFFFFFFFFu, v, off);
        if (lane == 0)
            out[0] = v * (1.0f / ((float)NROW * (float)NCOL));
    }
}

extern "C" void kernel_launch(void* const* d_in, const int* in_sizes, int n_in,
                              void* d_out, int out_size) {
    const float* pred = (const float*)d_in[0];
    const float* tgt  = (const float*)d_in[1];
    float* out = (float*)d_out;

    // 4 launches/call so ncu's "-s 5 -c 1" (launch idx 5 = replay's 2nd
    // launch) profiles sort_mse_kernel instead of the reduce.
    nop_kernel<<<1, 32>>>();
    sort_mse_kernel<<<NROW, T>>>(pred, tgt);
    final_reduce_kernel<<<1, 1024>>>(out);
    nop_kernel<<<1, 32>>>();
}

// round 5
// speedup vs baseline: 1.4524x; 1.4524x over previous
#include <cuda_runtime.h>

#define NCOL 2048
#define NROW 8192
#define T 128
#define V 16
#define SSTRIDE 20   // 16 data floats + 4 pad -> conflict-free float4 smem

__device__ float g_partial[NROW];

__device__ __forceinline__ void cswap_asc(float& a, float& b) {
    float lo = fminf(a, b);
    float hi = fmaxf(a, b);
    a = lo; b = hi;
}
__device__ __forceinline__ void cswap_desc(float& a, float& b) {
    float lo = fminf(a, b);
    float hi = fmaxf(a, b);
    a = hi; b = lo;
}

// Ascending bitonic merge of 16 register elements (strides 8,4,2,1).
__device__ __forceinline__ void merge16_asc(float v[V]) {
    #pragma unroll
    for (int j = 8; j >= 1; j >>= 1) {
        #pragma unroll
        for (int i = 0; i < V; i++)
            if ((i & j) == 0) cswap_asc(v[i], v[i | j]);
    }
}

// Bitonic phases k=2,4,8 with compile-time directions (i = 16*tid + e,
// so bits 2,4,8 of i are bits of e).
__device__ __forceinline__ void sort16_pre(float v[V]) {
    // k=2
    #pragma unroll
    for (int e = 0; e < V; e += 2) {
        if (e & 2) cswap_desc(v[e], v[e + 1]);
        else       cswap_asc (v[e], v[e + 1]);
    }
    // k=4
    #pragma unroll
    for (int j = 2; j >= 1; j >>= 1) {
        #pragma unroll
        for (int i = 0; i < V; i++)
            if ((i & j) == 0) {
                if (i & 4) cswap_desc(v[i], v[i | j]);
                else       cswap_asc (v[i], v[i | j]);
            }
    }
    // k=8
    #pragma unroll
    for (int j = 4; j >= 1; j >>= 1) {
        #pragma unroll
        for (int i = 0; i < V; i++)
            if ((i & j) == 0) {
                if (i & 8) cswap_desc(v[i], v[i | j]);
                else       cswap_asc (v[i], v[i | j]);
            }
    }
}

// Sign-space transition into thread-phase KM (element k = 16*KM):
// flip sign iff the direction bit changed vs previous phase.
template<int KM>
__device__ __forceinline__ void flip_into(float yp[V], float yt[V], const int tid) {
    const bool flip = (((tid & KM) != 0) != ((tid & (KM >> 1)) != 0));
    const float s = flip ? -1.0f : 1.0f;
    #pragma unroll
    for (int e = 0; e < V; e++) { yp[e] *= s; yt[e] *= s; }
}

// One bitonic phase in ascending sign-space. d>=32 crosses the warp
// boundary (128 threads = 4 warps) -> smem; d<=16 -> warp shuffle;
// then in-register tail (j=8,4,2,1).
template<int KM>
__device__ __forceinline__ void phase(float yp[V], float yt[V], const int tid,
                                      float (&bufp)[2][T * SSTRIDE],
                                      float (&buft)[2][T * SSTRIDE],
                                      int& ph) {
    #pragma unroll
    for (int d = KM / 2; d >= 1; d >>= 1) {
        const bool keep_lo = ((tid & d) == 0);
        if (d >= 32) {
            float4* sp4 = (float4*)&bufp[ph][tid * SSTRIDE];
            float4* st4 = (float4*)&buft[ph][tid * SSTRIDE];
            #pragma unroll
            for (int q = 0; q < 4; q++) {
                sp4[q] = make_float4(yp[4*q], yp[4*q+1], yp[4*q+2], yp[4*q+3]);
                st4[q] = make_float4(yt[4*q], yt[4*q+1], yt[4*q+2], yt[4*q+3]);
            }
            __syncthreads();

            const int ptn = tid ^ d;
            const float4* pp4 = (const float4*)&bufp[ph][ptn * SSTRIDE];
            const float4* pt4 = (const float4*)&buft[ph][ptn * SSTRIDE];
            #pragma unroll
            for (int q = 0; q < 4; q++) {
                float4 a = pp4[q];
                float4 b = pt4[q];
                float op[4] = {a.x, a.y, a.z, a.w};
                float ot[4] = {b.x, b.y, b.z, b.w};
                #pragma unroll
                for (int c = 0; c < 4; c++) {
                    int e = 4*q + c;
                    yp[e] = keep_lo ? fminf(yp[e], op[c]) : fmaxf(yp[e], op[c]);
                    yt[e] = keep_lo ? fminf(yt[e], ot[c]) : fmaxf(yt[e], ot[c]);
                }
            }
            ph ^= 1;
        } else {
            #pragma unroll
            for (int e = 0; e < V; e++) {
                float o1 = __shfl_xor_sync(0xFFFFFFFFu, yp[e], d);
                float o2 = __shfl_xor_sync(0xFFFFFFFFu, yt[e], d);
                yp[e] = keep_lo ? fminf(yp[e], o1) : fmaxf(yp[e], o1);
                yt[e] = keep_lo ? fminf(yt[e], o2) : fmaxf(yt[e], o2);
            }
        }
    }
    merge16_asc(yp);
    merge16_asc(yt);
}

__global__ __launch_bounds__(T)
void sort_mse_kernel(const float* __restrict__ pred,
                     const float* __restrict__ tgt) {
    __shared__ float bufp[2][T * SSTRIDE];
    __shared__ float buft[2][T * SSTRIDE];
    __shared__ float swarp[T / 32];

    const int row = blockIdx.x;
    const int tid = threadIdx.x;

    float yp[V], yt[V];

    // Coalesced vectorized load: thread owns elements [16*tid, 16*tid+15].
    {
        const float4* p4 = (const float4*)(pred + (size_t)row * NCOL) + tid * 4;
        const float4* t4 = (const float4*)(tgt  + (size_t)row * NCOL) + tid * 4;
        #pragma unroll
        for (int q = 0; q < 4; q++) {
            float4 a = p4[q];
            yp[4*q] = a.x; yp[4*q+1] = a.y; yp[4*q+2] = a.z; yp[4*q+3] = a.w;
            float4 b = t4[q];
            yt[4*q] = b.x; yt[4*q+1] = b.y; yt[4*q+2] = b.z; yt[4*q+3] = b.w;
        }
    }

    // k=2..8 compile-time in natural space.
    sort16_pre(yp);
    sort16_pre(yt);

    // Enter sign space for k=16: descending iff (tid & 1).
    {
        const float s = (tid & 1) ? -1.0f : 1.0f;
        #pragma unroll
        for (int e = 0; e < V; e++) { yp[e] *= s; yt[e] *= s; }
    }
    merge16_asc(yp);
    merge16_asc(yt);

    int ph = 0;
    flip_into<2>(yp, yt, tid);   phase<2>(yp, yt, tid, bufp, buft, ph);
    flip_into<4>(yp, yt, tid);   phase<4>(yp, yt, tid, bufp, buft, ph);
    flip_into<8>(yp, yt, tid);   phase<8>(yp, yt, tid, bufp, buft, ph);
    flip_into<16>(yp, yt, tid);  phase<16>(yp, yt, tid, bufp, buft, ph);
    flip_into<32>(yp, yt, tid);  phase<32>(yp, yt, tid, bufp, buft, ph);
    flip_into<64>(yp, yt, tid);  phase<64>(yp, yt, tid, bufp, buft, ph);
    flip_into<128>(yp, yt, tid); phase<128>(yp, yt, tid, bufp, buft, ph);
    // Final phase (k=2048) ascends for all tid<128 -> natural space, sorted.

    float s = 0.0f;
    #pragma unroll
    for (int e = 0; e < V; e++) {
        float d = yp[e] - yt[e];
        s = fmaf(d, d, s);
    }

    #pragma unroll
    for (int off = 16; off > 0; off >>= 1)
        s += __shfl_xor_sync(0xFFFFFFFFu, s, off);

    const int lane = tid & 31;
    const int wid  = tid >> 5;
    if (lane == 0) swarp[wid] = s;
    __syncthreads();

    if (wid == 0) {
        float v = (lane < T / 32) ? swarp[lane] : 0.0f;
        #pragma unroll
        for (int off = 2; off > 0; off >>= 1)
            v += __shfl_xor_sync(0xFFFFFFFFu, v, off);
        if (lane == 0) g_partial[row] = v;
    }
}

__global__ void final_reduce_kernel(float* __restrict__ out) {
    __shared__ float swarp[32];
    const int tid = threadIdx.x;

    float s = 0.0f;
    #pragma unroll
    for (int i = tid; i < NROW; i += 1024)
        s += g_partial[i];

    #pragma unroll
    for (int off = 16; off > 0; off >>= 1)
        s += __shfl_xor_sync(0xFFFFFFFFu, s, off);

    const int lane = tid & 31;
    const int wid  = tid >> 5;
    if (lane == 0) swarp[wid] = s;
    __syncthreads();

    if (wid == 0) {
        float v = swarp[lane];
        #pragma unroll
        for (int off = 16; off > 0; off >>= 1)
            v += __shfl_xor_sync(0xFFFFFFFFu, v, off);
        if (lane == 0)
            out[0] = v * (1.0f / ((float)NROW * (float)NCOL));
    }
}

extern "C" void kernel_launch(void* const* d_in, const int* in_sizes, int n_in,
                              void* d_out, int out_size) {
    const float* pred = (const float*)d_in[0];
    const float* tgt  = (const float*)d_in[1];
    float* out = (float*)d_out;

    sort_mse_kernel<<<NROW, T>>>(pred, tgt);
    final_reduce_kernel<<<1, 1024>>>(out);
}

// round 6
// speedup vs baseline: 1.4533x; 1.0006x over previous
#include <cuda_runtime.h>

#define NCOL 2048
#define NROW 8192
#define T 64
#define V 32
#define SSTRIDE 36   // 32 data floats + 4 pad -> conflict-free float4 smem

__device__ float g_partial[NROW];

__device__ __forceinline__ void cswap_asc(float& a, float& b) {
    float lo = fminf(a, b);
    float hi = fmaxf(a, b);
    a = lo; b = hi;
}
__device__ __forceinline__ void cswap_desc(float& a, float& b) {
    float lo = fminf(a, b);
    float hi = fmaxf(a, b);
    a = hi; b = lo;
}

// Ascending bitonic merge of 32 register elements (strides 16..1).
__device__ __forceinline__ void merge32_asc(float v[V]) {
    #pragma unroll
    for (int j = 16; j >= 1; j >>= 1) {
        #pragma unroll
        for (int i = 0; i < V; i++)
            if ((i & j) == 0) cswap_asc(v[i], v[i | j]);
    }
}

// Bitonic phases k=2..16: directions depend only on element-index bits
// (i = 32*tid + e, bits 1..4 of i are bits of e) -> fully compile-time.
__device__ __forceinline__ void sort32_pre(float v[V]) {
    #pragma unroll
    for (int k = 2; k <= 16; k <<= 1) {
        #pragma unroll
        for (int j = k >> 1; j >= 1; j >>= 1) {
            #pragma unroll
            for (int i = 0; i < V; i++)
                if ((i & j) == 0) {
                    if (i & k) cswap_desc(v[i], v[i | j]);
                    else       cswap_asc (v[i], v[i | j]);
                }
        }
    }
}

// Sign-space transition into thread-phase KM (element k = 32*KM):
// flip sign iff the direction bit changed vs previous phase (KM/2).
template<int KM>
__device__ __forceinline__ void flip_into(float yp[V], float yt[V], const int tid) {
    const bool flip = (((tid & KM) != 0) != ((tid & (KM >> 1)) != 0));
    const float s = flip ? -1.0f : 1.0f;
    #pragma unroll
    for (int e = 0; e < V; e++) { yp[e] *= s; yt[e] *= s; }
}

// One bitonic phase (element k = 32*KM) in ascending sign-space.
// d=32 crosses the warp boundary (T=64 -> 2 warps): smem, single barrier.
// d<=16: warp shuffle. Tail (j=16..1): registers.
template<int KM>
__device__ __forceinline__ void phase(float yp[V], float yt[V], const int tid,
                                      float (&bufp)[T * SSTRIDE],
                                      float (&buft)[T * SSTRIDE]) {
    #pragma unroll
    for (int d = KM / 2; d >= 1; d >>= 1) {
        const bool keep_lo = ((tid & d) == 0);
        if (d >= 32) {
            float4* sp4 = (float4*)&bufp[tid * SSTRIDE];
            float4* st4 = (float4*)&buft[tid * SSTRIDE];
            #pragma unroll
            for (int q = 0; q < 8; q++) {
                sp4[q] = make_float4(yp[4*q], yp[4*q+1], yp[4*q+2], yp[4*q+3]);
                st4[q] = make_float4(yt[4*q], yt[4*q+1], yt[4*q+2], yt[4*q+3]);
            }
            __syncthreads();

            const int ptn = tid ^ d;
            const float4* pp4 = (const float4*)&bufp[ptn * SSTRIDE];
            const float4* pt4 = (const float4*)&buft[ptn * SSTRIDE];
            #pragma unroll
            for (int q = 0; q < 8; q++) {
                float4 a = pp4[q];
                float4 b = pt4[q];
                float op[4] = {a.x, a.y, a.z, a.w};
                float ot[4] = {b.x, b.y, b.z, b.w};
                #pragma unroll
                for (int c = 0; c < 4; c++) {
                    int e = 4*q + c;
                    yp[e] = keep_lo ? fminf(yp[e], op[c]) : fmaxf(yp[e], op[c]);
                    yt[e] = keep_lo ? fminf(yt[e], ot[c]) : fmaxf(yt[e], ot[c]);
                }
            }
            // Buffer is used exactly once in the whole kernel -> no second
            // barrier needed.
        } else {
            #pragma unroll
            for (int e = 0; e < V; e++) {
                float o1 = __shfl_xor_sync(0xFFFFFFFFu, yp[e], d);
                float o2 = __shfl_xor_sync(0xFFFFFFFFu, yt[e], d);
                yp[e] = keep_lo ? fminf(yp[e], o1) : fmaxf(yp[e], o1);
                yt[e] = keep_lo ? fminf(yt[e], o2) : fmaxf(yt[e], o2);
            }
        }
    }
    merge32_asc(yp);
    merge32_asc(yt);
}

__global__ __launch_bounds__(T)
void sort_mse_kernel(const float* __restrict__ pred,
                     const float* __restrict__ tgt) {
    __shared__ float bufp[T * SSTRIDE];
    __shared__ float buft[T * SSTRIDE];
    __shared__ float swarp[T / 32];

    const int row = blockIdx.x;
    const int tid = threadIdx.x;

    float yp[V], yt[V];

    // Coalesced vectorized load: thread owns elements [32*tid, 32*tid+31].
    {
        const float4* p4 = (const float4*)(pred + (size_t)row * NCOL) + tid * 8;
        const float4* t4 = (const float4*)(tgt  + (size_t)row * NCOL) + tid * 8;
        #pragma unroll
        for (int q = 0; q < 8; q++) {
            float4 a = p4[q];
            yp[4*q] = a.x; yp[4*q+1] = a.y; yp[4*q+2] = a.z; yp[4*q+3] = a.w;
            float4 b = t4[q];
            yt[4*q] = b.x; yt[4*q+1] = b.y; yt[4*q+2] = b.z; yt[4*q+3] = b.w;
        }
    }

    // k=2..16 compile-time in natural space.
    sort32_pre(yp);
    sort32_pre(yt);

    // Enter sign space for k=32: descending iff (tid & 1).
    {
        const float s = (tid & 1) ? -1.0f : 1.0f;
        #pragma unroll
        for (int e = 0; e < V; e++) { yp[e] *= s; yt[e] *= s; }
    }
    merge32_asc(yp);
    merge32_asc(yt);

    flip_into<2>(yp, yt, tid);  phase<2>(yp, yt, tid, bufp, buft);
    flip_into<4>(yp, yt, tid);  phase<4>(yp, yt, tid, bufp, buft);
    flip_into<8>(yp, yt, tid);  phase<8>(yp, yt, tid, bufp, buft);
    flip_into<16>(yp, yt, tid); phase<16>(yp, yt, tid, bufp, buft);
    flip_into<32>(yp, yt, tid); phase<32>(yp, yt, tid, bufp, buft);
    flip_into<64>(yp, yt, tid); phase<64>(yp, yt, tid, bufp, buft);
    // Final phase (k=2048) ascends for all tid<64 -> natural space, sorted.

    float s = 0.0f;
    #pragma unroll
    for (int e = 0; e < V; e++) {
        float d = yp[e] - yt[e];
        s = fmaf(d, d, s);
    }

    #pragma unroll
    for (int off = 16; off > 0; off >>= 1)
        s += __shfl_xor_sync(0xFFFFFFFFu, s, off);

    const int lane = tid & 31;
    const int wid  = tid >> 5;
    if (lane == 0) swarp[wid] = s;
    __syncthreads();

    if (tid == 0) g_partial[row] = swarp[0] + swarp[1];
}

__global__ void final_reduce_kernel(float* __restrict__ out) {
    __shared__ float swarp[32];
    const int tid = threadIdx.x;

    float s = 0.0f;
    #pragma unroll
    for (int i = tid; i < NROW; i += 1024)
        s += g_partial[i];

    #pragma unroll
    for (int off = 16; off > 0; off >>= 1)
        s += __shfl_xor_sync(0xFFFFFFFFu, s, off);

    const int lane = tid & 31;
    const int wid  = tid >> 5;
    if (lane == 0) swarp[wid] = s;
    __syncthreads();

    if (wid == 0) {
        float v = swarp[lane];
        #pragma unroll
        for (int off = 16; off > 0; off >>= 1)
            v += __shfl_xor_sync(0xFFFFFFFFu, v, off);
        if (lane == 0)
            out[0] = v * (1.0f / ((float)NROW * (float)NCOL));
    }
}

extern "C" void kernel_launch(void* const* d_in, const int* in_sizes, int n_in,
                              void* d_out, int out_size) {
    const float* pred = (const float*)d_in[0];
    const float* tgt  = (const float*)d_in[1];
    float* out = (float*)d_out;

    sort_mse_kernel<<<NROW, T>>>(pred, tgt);
    final_reduce_kernel<<<1, 1024>>>(out);
}

// round 9
// speedup vs baseline: 1.4672x; 1.0096x over previous
#include <cuda_runtime.h>

#define NCOL 2048
#define NROW 8192
#define T 64
#define V 32
#define SSTRIDE 36   // 32 data floats + 4 pad -> conflict-free float4 smem

__device__ float g_acc = 0.0f;
__device__ unsigned int g_ticket = 0;

__device__ __forceinline__ void cswap_asc(float& a, float& b) {
    float lo = fminf(a, b);
    float hi = fmaxf(a, b);
    a = lo; b = hi;
}
__device__ __forceinline__ void cswap_desc(float& a, float& b) {
    float lo = fminf(a, b);
    float hi = fmaxf(a, b);
    a = hi; b = lo;
}

__device__ __forceinline__ void scale2(float yp[V], float yt[V], float s) {
    #pragma unroll
    for (int e = 0; e < V; e++) { yp[e] *= s; yt[e] *= s; }
}

// Ascending bitonic merge of 32 register elements (strides 16..1).
__device__ __forceinline__ void merge32_asc(float v[V]) {
    #pragma unroll
    for (int j = 16; j >= 1; j >>= 1) {
        #pragma unroll
        for (int i = 0; i < V; i++)
            if ((i & j) == 0) cswap_asc(v[i], v[i | j]);
    }
}

// Bitonic phases k=2..16: directions are compile-time (bits of e).
__device__ __forceinline__ void sort32_pre(float v[V]) {
    #pragma unroll
    for (int k = 2; k <= 16; k <<= 1) {
        #pragma unroll
        for (int j = k >> 1; j >= 1; j >>= 1) {
            #pragma unroll
            for (int i = 0; i < V; i++)
                if ((i & j) == 0) {
                    if (i & k) cswap_desc(v[i], v[i | j]);
                    else       cswap_asc (v[i], v[i | j]);
                }
        }
    }
}

// Phase-sign transition into thread-phase KM.
template<int KM>
__device__ __forceinline__ void flip_into(float yp[V], float yt[V], const int tid) {
    const bool flip = (((tid & KM) != 0) != ((tid & (KM >> 1)) != 0));
    scale2(yp, yt, flip ? -1.0f : 1.0f);
}

// One bitonic phase in ascending phase-sign space, with a second
// PASS-sign layer for cross-thread passes: values are stored negated on
// threads with the current stride bit set, making every comparator a
// uniform  z = fminf(z, -partner)  -- single FMNMX, no select.
template<int KM>
__device__ __forceinline__ void phase(float yp[V], float yt[V], const int tid,
                                      float (&bufp)[T * SSTRIDE],
                                      float (&buft)[T * SSTRIDE]) {
    // Enter pass-sign space for the first stride d = KM/2.
    {
        const float s = (tid & (KM / 2)) ? -1.0f : 1.0f;
        scale2(yp, yt, s);
    }

    #pragma unroll
    for (int d = KM / 2; d >= 1; d >>= 1) {
        if (d >= 32) {
            // Cross-warp exchange through shared (used once per kernel).
            float4* sp4 = (float4*)&bufp[tid * SSTRIDE];
            float4* st4 = (float4*)&buft[tid * SSTRIDE];
            #pragma unroll
            for (int q = 0; q < 8; q++) {
                sp4[q] = make_float4(yp[4*q], yp[4*q+1], yp[4*q+2], yp[4*q+3]);
                st4[q] = make_float4(yt[4*q], yt[4*q+1], yt[4*q+2], yt[4*q+3]);
            }
            __syncthreads();

            const int ptn = tid ^ d;
            const float4* pp4 = (const float4*)&bufp[ptn * SSTRIDE];
            const float4* pt4 = (const float4*)&buft[ptn * SSTRIDE];
            #pragma unroll
            for (int q = 0; q < 8; q++) {
                float4 a = pp4[q];
                float4 b = pt4[q];
                yp[4*q+0] = fminf(yp[4*q+0], -a.x);
                yp[4*q+1] = fminf(yp[4*q+1], -a.y);
                yp[4*q+2] = fminf(yp[4*q+2], -a.z);
                yp[4*q+3] = fminf(yp[4*q+3], -a.w);
                yt[4*q+0] = fminf(yt[4*q+0], -b.x);
                yt[4*q+1] = fminf(yt[4*q+1], -b.y);
                yt[4*q+2] = fminf(yt[4*q+2], -b.z);
                yt[4*q+3] = fminf(yt[4*q+3], -b.w);
            }
        } else {
            #pragma unroll
            for (int e = 0; e < V; e++) {
                float o1 = __shfl_xor_sync(0xFFFFFFFFu, yp[e], d);
                float o2 = __shfl_xor_sync(0xFFFFFFFFu, yt[e], d);
                yp[e] = fminf(yp[e], -o1);
                yt[e] = fminf(yt[e], -o2);
            }
        }

        // Transition: next stride d/2 (or exit pass-sign space when d==1).
        const int nd = d >> 1;
        const bool flip = nd ? (((tid & d) != 0) != ((tid & nd) != 0))
                             : ((tid & 1) != 0);
        scale2(yp, yt, flip ? -1.0f : 1.0f);
    }

    merge32_asc(yp);
    merge32_asc(yt);
}

__global__ __launch_bounds__(T)
void sort_mse_kernel(const float* __restrict__ pred,
                     const float* __restrict__ tgt,
                     float* __restrict__ out) {
    __shared__ float bufp[T * SSTRIDE];
    __shared__ float buft[T * SSTRIDE];
    __shared__ float swarp[T / 32];

    const int row = blockIdx.x;
    const int tid = threadIdx.x;

    float yp[V], yt[V];

    // Coalesced vectorized load: thread owns elements [32*tid, 32*tid+31].
    {
        const float4* p4 = (const float4*)(pred + (size_t)row * NCOL) + tid * 8;
        const float4* t4 = (const float4*)(tgt  + (size_t)row * NCOL) + tid * 8;
        #pragma unroll
        for (int q = 0; q < 8; q++) {
            float4 a = p4[q];
            yp[4*q] = a.x; yp[4*q+1] = a.y; yp[4*q+2] = a.z; yp[4*q+3] = a.w;
            float4 b = t4[q];
            yt[4*q] = b.x; yt[4*q+1] = b.y; yt[4*q+2] = b.z; yt[4*q+3] = b.w;
        }
    }

    // k=2..16 compile-time in natural space.
    sort32_pre(yp);
    sort32_pre(yt);

    // Enter phase-sign space for k=32: descending iff (tid & 1).
    scale2(yp, yt, (tid & 1) ? -1.0f : 1.0f);
    merge32_asc(yp);
    merge32_asc(yt);

    flip_into<2>(yp, yt, tid);  phase<2>(yp, yt, tid, bufp, buft);
    flip_into<4>(yp, yt, tid);  phase<4>(yp, yt, tid, bufp, buft);
    flip_into<8>(yp, yt, tid);  phase<8>(yp, yt, tid, bufp, buft);
    flip_into<16>(yp, yt, tid); phase<16>(yp, yt, tid, bufp, buft);
    flip_into<32>(yp, yt, tid); phase<32>(yp, yt, tid, bufp, buft);
    flip_into<64>(yp, yt, tid); phase<64>(yp, yt, tid, bufp, buft);
    // Final phase ascends for all tid<64 -> natural space, both rows sorted.

    float s = 0.0f;
    #pragma unroll
    for (int e = 0; e < V; e++) {
        float d = yp[e] - yt[e];
        s = fmaf(d, d, s);
    }

    #pragma unroll
    for (int off = 16; off > 0; off >>= 1)
        s += __shfl_xor_sync(0xFFFFFFFFu, s, off);

    const int lane = tid & 31;
    const int wid  = tid >> 5;
    if (lane == 0) swarp[wid] = s;
    __syncthreads();

    // Fused grid reduction: ticket pattern, last CTA writes + resets state
    // so every graph replay starts from the same state.
    if (tid == 0) {
        float partial = swarp[0] + swarp[1];
        atomicAdd(&g_acc, partial);
        __threadfence();
        unsigned int t = atomicAdd(&g_ticket, 1u);
        if (t == NROW - 1) {
            float total = atomicExch(&g_acc, 0.0f);  // read + reset
            out[0] = total * (1.0f / ((float)NROW * (float)NCOL));
            __threadfence();
            g_ticket = 0;
        }
    }
}

extern "C" void kernel_launch(void* const* d_in, const int* in_sizes, int n_in,
                              void* d_out, int out_size) {
    const float* pred = (const float*)d_in[0];
    const float* tgt  = (const float*)d_in[1];
    float* out = (float*)d_out;

    sort_mse_kernel<<<NROW, T>>>(pred, tgt, out);
}